// round 15
// baseline (speedup 1.0000x reference)
#include <cuda_runtime.h>

// SoftBCELoss, round 15: R11 (halo-by-shuffle) with dense unguarded main
// loop. input/target: [B, C=2, T=60000] fp32; out: 3 scalars.
//
// target_process == circular symmetric 7-tap conv
//   w = {0:1.328125, +-1:0.65625, +-2:0.3125, +-3:0.125}, then min(.,1)
// alpha = gamma = 0.5 -> per-channel loss = 0.5 * sum(bce) / (B*T)
// BCE in log2 domain (bare MUFU.LG2), *ln2 once at the end.
//
// BLK_X=5 -> stride 1280 pairs: 5 iterations are fully valid (j<=6399<7500)
// and run with NO validity predication and NO wrap ternary on the right
// halo; one peeled guarded tail iteration handles j in [6400,7500) plus the
// circular row wrap. Halo via __shfl, warp edges via 2 predicated loads.

#define NTHR    256
#define BLK_X   5
#define T4      15000                 // float4 groups per row (T = 60000)
#define J2      (T4 / 2)              // 7500 float4-pairs per row
#define STRIDEX (BLK_X * NTHR)        // 1280
#define NFULL   5                     // dense iterations: max j = 6399

__device__ float2       g_block[2560];   // partials, row*BLK_X + bx (log2 units)
__device__ unsigned int g_count = 0;     // wraps to 0 every full pass

__global__ __launch_bounds__(NTHR, 8)
void loss_r15(const float4* __restrict__ inp,
              const float4* __restrict__ tgt,
              float* __restrict__ out,
              int n_rows)
{
    const float W0 = 1.328125f, W1 = 0.65625f, W2 = 0.3125f, W3 = 0.125f;
    const unsigned FULL = 0xffffffffu;

    const int tid  = threadIdx.x;
    const int lane = tid & 31;
    const int row  = blockIdx.y;
    const int base = row * T4;
    const int j0   = blockIdx.x * NTHR + tid;

    float acc = 0.0f;   // log2-domain partial (negative)

    // ---------------- dense main loop: no validity logic ----------------
    #pragma unroll 1
    for (int it = 0; it < NFULL; it++) {
        const int j = j0 + it * STRIDEX;     // <= 6399 < J2 always
        const int g = 2 * j;

        const float4 i0 = __ldcs(&inp[base + g]);
        const float4 i1 = __ldcs(&inp[base + g + 1]);
        const float4 c0 = tgt[base + g];
        const float4 c1 = tgt[base + g + 1];

        // halo from neighbor lanes
        float e0 = __shfl_up_sync(FULL, c1.y, 1);     // tgt[8j-3]
        float e1 = __shfl_up_sync(FULL, c1.z, 1);
        float e2 = __shfl_up_sync(FULL, c1.w, 1);
        float f0 = __shfl_down_sync(FULL, c0.x, 1);   // tgt[8j+8]
        float f1 = __shfl_down_sync(FULL, c0.y, 1);
        float f2 = __shfl_down_sync(FULL, c0.z, 1);

        // warp-edge fixups (right edge never wraps here: g+2 <= 12800)
        if (lane == 0) {
            const int gPrev = (g == 0) ? (T4 - 1) : (g - 1);
            const float4 pm = tgt[base + gPrev];
            e0 = pm.y; e1 = pm.z; e2 = pm.w;
        }
        if (lane == 31) {
            const float4 pn = tgt[base + g + 2];
            f0 = pn.x; f1 = pn.y; f2 = pn.z;
        }

        const float w0 = e0, w1 = e1, w2 = e2;
        const float w3 = c0.x, w4 = c0.y, w5 = c0.z, w6 = c0.w;
        const float w7 = c1.x, w8 = c1.y, w9 = c1.z, w10 = c1.w;
        const float w11 = f0, w12 = f1, w13 = f2;

        float tv[8];
        tv[0] = fminf(W0*w3  + W1*(w2+w4)  + W2*(w1+w5)  + W3*(w0+w6),  1.0f);
        tv[1] = fminf(W0*w4  + W1*(w3+w5)  + W2*(w2+w6)  + W3*(w1+w7),  1.0f);
        tv[2] = fminf(W0*w5  + W1*(w4+w6)  + W2*(w3+w7)  + W3*(w2+w8),  1.0f);
        tv[3] = fminf(W0*w6  + W1*(w5+w7)  + W2*(w4+w8)  + W3*(w3+w9),  1.0f);
        tv[4] = fminf(W0*w7  + W1*(w6+w8)  + W2*(w5+w9)  + W3*(w4+w10), 1.0f);
        tv[5] = fminf(W0*w8  + W1*(w7+w9)  + W2*(w6+w10) + W3*(w5+w11), 1.0f);
        tv[6] = fminf(W0*w9  + W1*(w8+w10) + W2*(w7+w11) + W3*(w6+w12), 1.0f);
        tv[7] = fminf(W0*w10 + W1*(w9+w11) + W2*(w8+w12) + W3*(w7+w13), 1.0f);

        const float pv[8] = {i0.x, i0.y, i0.z, i0.w, i1.x, i1.y, i1.z, i1.w};
        #pragma unroll
        for (int k = 0; k < 8; k++) {
            const float p   = pv[k];
            const float lg0 = __log2f(1.0f - p);   // bare MUFU.LG2
            const float lg1 = __log2f(p);
            acc += lg0 + tv[k] * (lg1 - lg0);       // bce = -ln2 * this
        }
    }

    // ---------------- peeled guarded tail: j in [6400, 7500) ----------------
    {
        const int  j     = j0 + NFULL * STRIDEX;
        const bool valid = (j < J2);
        const int  g     = 2 * j;

        float4 i0 = {0,0,0,0}, i1 = {0,0,0,0};
        float4 c0 = {0,0,0,0}, c1 = {0,0,0,0};
        if (valid) {
            i0 = __ldcs(&inp[base + g]);
            i1 = __ldcs(&inp[base + g + 1]);
            c0 = tgt[base + g];
            c1 = tgt[base + g + 1];
        }

        float e0 = __shfl_up_sync(FULL, c1.y, 1);
        float e1 = __shfl_up_sync(FULL, c1.z, 1);
        float e2 = __shfl_up_sync(FULL, c1.w, 1);
        float f0 = __shfl_down_sync(FULL, c0.x, 1);
        float f1 = __shfl_down_sync(FULL, c0.y, 1);
        float f2 = __shfl_down_sync(FULL, c0.z, 1);

        if (valid && lane == 0) {
            const float4 pm = tgt[base + g - 1];   // j >= 6400 -> no wrap
            e0 = pm.y; e1 = pm.z; e2 = pm.w;
        }
        if (valid && (lane == 31 || j == J2 - 1)) {
            const int gNext = (g + 2 == T4) ? 0 : (g + 2);
            const float4 pn = tgt[base + gNext];
            f0 = pn.x; f1 = pn.y; f2 = pn.z;
        }

        if (valid) {
            const float w0 = e0, w1 = e1, w2 = e2;
            const float w3 = c0.x, w4 = c0.y, w5 = c0.z, w6 = c0.w;
            const float w7 = c1.x, w8 = c1.y, w9 = c1.z, w10 = c1.w;
            const float w11 = f0, w12 = f1, w13 = f2;

            float tv[8];
            tv[0] = fminf(W0*w3  + W1*(w2+w4)  + W2*(w1+w5)  + W3*(w0+w6),  1.0f);
            tv[1] = fminf(W0*w4  + W1*(w3+w5)  + W2*(w2+w6)  + W3*(w1+w7),  1.0f);
            tv[2] = fminf(W0*w5  + W1*(w4+w6)  + W2*(w3+w7)  + W3*(w2+w8),  1.0f);
            tv[3] = fminf(W0*w6  + W1*(w5+w7)  + W2*(w4+w8)  + W3*(w3+w9),  1.0f);
            tv[4] = fminf(W0*w7  + W1*(w6+w8)  + W2*(w5+w9)  + W3*(w4+w10), 1.0f);
            tv[5] = fminf(W0*w8  + W1*(w7+w9)  + W2*(w6+w10) + W3*(w5+w11), 1.0f);
            tv[6] = fminf(W0*w9  + W1*(w8+w10) + W2*(w7+w11) + W3*(w6+w12), 1.0f);
            tv[7] = fminf(W0*w10 + W1*(w9+w11) + W2*(w8+w12) + W3*(w7+w13), 1.0f);

            const float pv[8] = {i0.x, i0.y, i0.z, i0.w, i1.x, i1.y, i1.z, i1.w};
            #pragma unroll
            for (int k = 0; k < 8; k++) {
                const float p   = pv[k];
                const float lg0 = __log2f(1.0f - p);
                const float lg1 = __log2f(p);
                acc += lg0 + tv[k] * (lg1 - lg0);
            }
        }
    }

    // ---- block reduce (log2 units) ----
    #pragma unroll
    for (int o = 16; o > 0; o >>= 1)
        acc += __shfl_xor_sync(FULL, acc, o);

    __shared__ float swarp[NTHR / 32];
    const int wid = tid >> 5;
    if (lane == 0) swarp[wid] = acc;
    __syncthreads();

    const int n_blocks = n_rows * BLK_X;

    __shared__ bool s_last;
    if (tid == 0) {
        float a = 0.0f;
        #pragma unroll
        for (int i = 0; i < NTHR / 32; i++) a += swarp[i];
        // channel = row & 1 (rows are [B][C], C = 2)
        float2 v = (row & 1) ? make_float2(0.0f, a) : make_float2(a, 0.0f);
        g_block[row * BLK_X + blockIdx.x] = v;
        __threadfence();
        unsigned t = atomicInc(&g_count, (unsigned)(n_blocks - 1));
        s_last = (t == (unsigned)(n_blocks - 1));
    }
    __syncthreads();

    if (!s_last) return;

    // ---- last block: deterministic final reduction ----
    double a = 0.0, b = 0.0;
    for (int i = tid; i < n_blocks; i += NTHR) {
        float2 v = g_block[i];
        a += (double)v.x;
        b += (double)v.y;
    }
    __shared__ double sa[NTHR], sb[NTHR];
    sa[tid] = a;
    sb[tid] = b;
    __syncthreads();
    for (int o = NTHR / 2; o > 0; o >>= 1) {
        if (tid < o) { sa[tid] += sa[tid + o]; sb[tid] += sb[tid + o]; }
        __syncthreads();
    }
    if (tid == 0) {
        const double LN2 = 0.6931471805599453;
        double dn = (double)n_rows * 0.5 * (double)(4 * T4);  // num = B*T
        float tb = (float)(-0.5 * LN2 * sa[0] / dn);
        float td = (float)(-0.5 * LN2 * sb[0] / dn);
        out[0] = tb + td;
        out[1] = tb;
        out[2] = td;
    }
}

extern "C" void kernel_launch(void* const* d_in, const int* in_sizes, int n_in,
                              void* d_out, int out_size)
{
    const float4* inp = (const float4*)d_in[0];
    const float4* tgt = (const float4*)d_in[1];
    const int n      = in_sizes[0];          // B*C*T
    const int n_rows = n / (4 * T4);         // B*C (512 for B=256)
    dim3 grid(BLK_X, n_rows);
    loss_r15<<<grid, NTHR>>>(inp, tgt, (float*)d_out, n_rows);
}

// round 17
// speedup vs baseline: 1.0260x; 1.0260x over previous
#include <cuda_runtime.h>

// SoftBCELoss, round 17 (resubmit of R16 after infra flake): R11 halo-by-
// shuffle + Blackwell 256-bit global loads (ld.global.v8.f32 -> LDG.E.256):
// payload request count halved for identical bytes.
//
// input/target: [B, C=2, T=60000] fp32; out: 3 scalars (total, beat, down).
// target_process == circular symmetric 7-tap conv
//   w = {0:1.328125, +-1:0.65625, +-2:0.3125, +-3:0.125}, then min(.,1)
// alpha = gamma = 0.5 -> per-channel loss = 0.5 * sum(bce) / (B*T)
// BCE in log2 domain (bare MUFU.LG2), *ln2 once at the end.

#define NTHR    256
#define BLK_X   4
#define T4      15000                 // float4 groups per row (T = 60000)
#define J2      (T4 / 2)              // 7500 float4-pairs per row
#define STRIDEX (BLK_X * NTHR)        // 1024
#define NITER   ((J2 + STRIDEX - 1) / STRIDEX)   // 8

__device__ float2       g_block[4096];   // partials, row*BLK_X + bx (log2 units)
__device__ unsigned int g_count = 0;     // wraps to 0 every full pass

struct F8 { float4 a, b; };

// 32B-aligned 256-bit loads (sm_100+). Row bases and 2*j offsets are 32B-aligned.
__device__ __forceinline__ F8 ldg256_cs(const float4* p) {
    F8 r;
    asm volatile("ld.global.cs.v8.f32 {%0,%1,%2,%3,%4,%5,%6,%7}, [%8];"
        : "=f"(r.a.x), "=f"(r.a.y), "=f"(r.a.z), "=f"(r.a.w),
          "=f"(r.b.x), "=f"(r.b.y), "=f"(r.b.z), "=f"(r.b.w)
        : "l"(p));
    return r;
}
__device__ __forceinline__ F8 ldg256(const float4* p) {
    F8 r;
    asm volatile("ld.global.v8.f32 {%0,%1,%2,%3,%4,%5,%6,%7}, [%8];"
        : "=f"(r.a.x), "=f"(r.a.y), "=f"(r.a.z), "=f"(r.a.w),
          "=f"(r.b.x), "=f"(r.b.y), "=f"(r.b.z), "=f"(r.b.w)
        : "l"(p));
    return r;
}

__global__ __launch_bounds__(NTHR, 8)
void loss_r17(const float4* __restrict__ inp,
              const float4* __restrict__ tgt,
              float* __restrict__ out,
              int n_rows)
{
    const float W0 = 1.328125f, W1 = 0.65625f, W2 = 0.3125f, W3 = 0.125f;
    const unsigned FULL = 0xffffffffu;

    const int tid  = threadIdx.x;
    const int lane = tid & 31;
    const int row  = blockIdx.y;
    const int base = row * T4;
    const int j0   = blockIdx.x * NTHR + tid;

    float acc = 0.0f;   // log2-domain partial (negative)

    #pragma unroll 1
    for (int it = 0; it < NITER; it++) {
        const int  j     = j0 + it * STRIDEX;
        const bool valid = (j < J2);
        const int  g     = 2 * j;

        F8 ip = {{0,0,0,0},{0,0,0,0}};
        F8 tg = {{0,0,0,0},{0,0,0,0}};
        if (valid) {
            ip = ldg256_cs(&inp[base + g]);   // 8 probs, evict-first
            tg = ldg256(&tgt[base + g]);      // 8 targets, default caching
        }
        const float4 i0 = ip.a, i1 = ip.b;
        const float4 c0 = tg.a, c1 = tg.b;

        // halo from neighbor lanes (all 32 lanes converged -> full mask OK)
        float e0 = __shfl_up_sync(FULL, c1.y, 1);     // tgt[8j-3]
        float e1 = __shfl_up_sync(FULL, c1.z, 1);     // tgt[8j-2]
        float e2 = __shfl_up_sync(FULL, c1.w, 1);     // tgt[8j-1]
        float f0 = __shfl_down_sync(FULL, c0.x, 1);   // tgt[8j+8]
        float f1 = __shfl_down_sync(FULL, c0.y, 1);   // tgt[8j+9]
        float f2 = __shfl_down_sync(FULL, c0.z, 1);   // tgt[8j+10]

        // warp-edge fixups: single-lane predicated loads
        if (valid && lane == 0) {
            const int gPrev = (g == 0) ? (T4 - 1) : (g - 1);
            const float4 pm = tgt[base + gPrev];
            e0 = pm.y; e1 = pm.z; e2 = pm.w;
        }
        if (valid && (lane == 31 || j == J2 - 1)) {
            const int gNext = (g + 2 == T4) ? 0 : (g + 2);
            const float4 pn = tgt[base + gNext];
            f0 = pn.x; f1 = pn.y; f2 = pn.z;
        }

        if (valid) {
            // window tgt[8j-3 .. 8j+10] -> w[0..13]
            const float w0 = e0, w1 = e1, w2 = e2;
            const float w3 = c0.x, w4 = c0.y, w5 = c0.z, w6 = c0.w;
            const float w7 = c1.x, w8 = c1.y, w9 = c1.z, w10 = c1.w;
            const float w11 = f0, w12 = f1, w13 = f2;

            float tv[8];
            tv[0] = fminf(W0*w3  + W1*(w2+w4)  + W2*(w1+w5)  + W3*(w0+w6),  1.0f);
            tv[1] = fminf(W0*w4  + W1*(w3+w5)  + W2*(w2+w6)  + W3*(w1+w7),  1.0f);
            tv[2] = fminf(W0*w5  + W1*(w4+w6)  + W2*(w3+w7)  + W3*(w2+w8),  1.0f);
            tv[3] = fminf(W0*w6  + W1*(w5+w7)  + W2*(w4+w8)  + W3*(w3+w9),  1.0f);
            tv[4] = fminf(W0*w7  + W1*(w6+w8)  + W2*(w5+w9)  + W3*(w4+w10), 1.0f);
            tv[5] = fminf(W0*w8  + W1*(w7+w9)  + W2*(w6+w10) + W3*(w5+w11), 1.0f);
            tv[6] = fminf(W0*w9  + W1*(w8+w10) + W2*(w7+w11) + W3*(w6+w12), 1.0f);
            tv[7] = fminf(W0*w10 + W1*(w9+w11) + W2*(w8+w12) + W3*(w7+w13), 1.0f);

            const float pv[8] = {i0.x, i0.y, i0.z, i0.w, i1.x, i1.y, i1.z, i1.w};

            #pragma unroll
            for (int k = 0; k < 8; k++) {
                const float p   = pv[k];
                const float lg0 = __log2f(1.0f - p);   // bare MUFU.LG2
                const float lg1 = __log2f(p);
                acc += lg0 + tv[k] * (lg1 - lg0);       // bce = -ln2 * this
            }
        }
    }

    // ---- block reduce (log2 units) ----
    #pragma unroll
    for (int o = 16; o > 0; o >>= 1)
        acc += __shfl_xor_sync(FULL, acc, o);

    __shared__ float swarp[NTHR / 32];
    const int wid = tid >> 5;
    if (lane == 0) swarp[wid] = acc;
    __syncthreads();

    const int n_blocks = n_rows * BLK_X;

    __shared__ bool s_last;
    if (tid == 0) {
        float a = 0.0f;
        #pragma unroll
        for (int i = 0; i < NTHR / 32; i++) a += swarp[i];
        // channel = row & 1 (rows are [B][C], C = 2)
        float2 v = (row & 1) ? make_float2(0.0f, a) : make_float2(a, 0.0f);
        g_block[row * BLK_X + blockIdx.x] = v;
        __threadfence();
        unsigned t = atomicInc(&g_count, (unsigned)(n_blocks - 1));
        s_last = (t == (unsigned)(n_blocks - 1));
    }
    __syncthreads();

    if (!s_last) return;

    // ---- last block: deterministic final reduction ----
    double a = 0.0, b = 0.0;
    for (int i = tid; i < n_blocks; i += NTHR) {
        float2 v = g_block[i];
        a += (double)v.x;
        b += (double)v.y;
    }
    __shared__ double sa[NTHR], sb[NTHR];
    sa[tid] = a;
    sb[tid] = b;
    __syncthreads();
    for (int o = NTHR / 2; o > 0; o >>= 1) {
        if (tid < o) { sa[tid] += sa[tid + o]; sb[tid] += sb[tid + o]; }
        __syncthreads();
    }
    if (tid == 0) {
        const double LN2 = 0.6931471805599453;
        double dn = (double)n_rows * 0.5 * (double)(4 * T4);  // num = B*T
        float tb = (float)(-0.5 * LN2 * sa[0] / dn);
        float td = (float)(-0.5 * LN2 * sb[0] / dn);
        out[0] = tb + td;
        out[1] = tb;
        out[2] = td;
    }
}

extern "C" void kernel_launch(void* const* d_in, const int* in_sizes, int n_in,
                              void* d_out, int out_size)
{
    const float4* inp = (const float4*)d_in[0];
    const float4* tgt = (const float4*)d_in[1];
    const int n      = in_sizes[0];          // B*C*T
    const int n_rows = n / (4 * T4);         // B*C (512 for B=256)
    dim3 grid(BLK_X, n_rows);
    loss_r17<<<grid, NTHR>>>(inp, tgt, (float*)d_out, n_rows);
}